// round 7
// baseline (speedup 1.0000x reference)
#include <cuda_runtime.h>
#include <math.h>

// Problem shape (fixed): B=8, C=64, T=16, H=64, W=64, text_dim=768
#define NB 8
#define NC 64
#define NT 16
#define HW4 1024         // H*W/4 (float4 / longlong2 units per T-plane)
#define TD 768
#define NBC (NB*NC)      // 512

// Per-(b,c,t) sigmoid gates
__device__ float g_w[NBC * NT];   // 32 KB

__device__ __forceinline__ unsigned long long pack2(float v) {
    float2 f = make_float2(v, v);
    return *reinterpret_cast<unsigned long long*>(&f);
}

// ---------------------------------------------------------------------------
// Kernel 1: gates.  One block per c (64 blocks); Wf rows stay in registers,
// loop over the 8 batch rows of E (smem).  Wf read exactly once (3 MB).
// ---------------------------------------------------------------------------
__global__ __launch_bounds__(256) void gate_kernel(
    const float* __restrict__ E,    // (B, 768)
    const float* __restrict__ Wf,   // (C*T, 768)
    const float* __restrict__ bf)   // (C*T,)
{
    __shared__ float4 sE[NB][TD / 4];   // 24 KB

    const int c = blockIdx.x;
    const int g = threadIdx.x >> 4;      // row-in-c 0..15
    const int l = threadIdx.x & 15;      // lane within group

    for (int i = threadIdx.x; i < NB * (TD / 4); i += 256)
        ((float4*)sE)[i] = ((const float4*)E)[i];

    const int j = c * NT + g;
    const float4* w4 = (const float4*)(Wf + (size_t)j * TD);
    float4 wr[12];
    #pragma unroll
    for (int i = 0; i < 12; i++) wr[i] = w4[l + 16 * i];
    const float bj = bf[j];
    __syncthreads();

    #pragma unroll
    for (int b = 0; b < NB; b++) {
        float s = 0.0f;
        #pragma unroll
        for (int i = 0; i < 12; i++) {
            const float4 ev = sE[b][l + 16 * i];
            s = fmaf(ev.x, wr[i].x, s);
            s = fmaf(ev.y, wr[i].y, s);
            s = fmaf(ev.z, wr[i].z, s);
            s = fmaf(ev.w, wr[i].w, s);
        }
        #pragma unroll
        for (int o = 8; o; o >>= 1) s += __shfl_xor_sync(0xffffffffu, s, o);
        if (l == 0) {
            const float z = s + bj;
            g_w[(b * NC + c) * NT + g] = 1.0f / (1.0f + expf(-z));
        }
    }
}

// ---------------------------------------------------------------------------
// Kernel 2: streaming modulation with even/odd folding, register-dieted to
// 3 blocks/SM.  Pairwise load order + fold-as-it-lands keeps peak live regs
// ~= 64 (s/d) + temps: x[j],x[15-j] die exactly when sl/sh/dl/dh[j] are born.
// ---------------------------------------------------------------------------
__global__ __launch_bounds__(256, 3) void mod_kernel(
    const longlong2* __restrict__ r,    // float4 planes as 2x f32x2
    longlong2* __restrict__ out)
{
    __shared__ float sw[NT];
    __shared__ float sD[NT][NT];
    __shared__ unsigned long long sEm[8][8];   // duplicated (m,m) pairs
    __shared__ unsigned long long sOm[8][8];

    const int bc = blockIdx.x;
    const int u = blockIdx.y * 256 + threadIdx.x;        // [0, 1024)
    const size_t base = (size_t)bc * (NT * HW4) + u;

    // stage gates + DCT table first (cheap; needed by the E/O build)
    if (threadIdx.x < NT) sw[threadIdx.x] = g_w[bc * NT + threadIdx.x];
    {
        const int k = threadIdx.x >> 4;
        const int t = threadIdx.x & 15;
        const float sc = (k == 0) ? 0.25f : 0.35355339059327373f; // sqrt(1/16), sqrt(2/16)
        sD[k][t] = cosf(3.14159265358979323846f * ((float)t + 0.5f) * (float)k / 16.0f) * sc;
    }
    __syncthreads();

    // Front-batched streaming loads, pairwise order (j, 15-j)
    longlong2 xa[8], xb[8];
    #pragma unroll
    for (int j = 0; j < 8; j++) {
        xa[j] = __ldcs(r + base + (size_t)j * HW4);
        xb[j] = __ldcs(r + base + (size_t)(15 - j) * HW4);
    }

    // ---- E/O build in the load-latency shadow ----
    if (threadIdx.x < 128) {
        const int t   = (threadIdx.x >> 3) & 7;
        const int jj  = threadIdx.x & 7;
        const int odd = threadIdx.x >> 6;    // 0 -> E, 1 -> O
        float acc = 0.0f;
        #pragma unroll
        for (int m = 0; m < 8; m++) {
            const int k = 2 * m + odd;
            acc = fmaf(sD[k][t] * sw[k], sD[k][jj], acc);
        }
        const unsigned long long p = pack2(acc);
        if (odd) sOm[t][jj] = p; else sEm[t][jj] = p;
    }

    // ---- fold pair-by-pair (register-neutral: 8 regs die, 8 born) ----
    const unsigned long long NEG1 = pack2(-1.0f);
    unsigned long long sl[8], sh[8], dl[8], dh[8];
    #pragma unroll
    for (int j = 0; j < 8; j++) {
        const unsigned long long al = (unsigned long long)xa[j].x;
        const unsigned long long ah = (unsigned long long)xa[j].y;
        const unsigned long long bl = (unsigned long long)xb[j].x;
        const unsigned long long bh = (unsigned long long)xb[j].y;
        asm("add.rn.f32x2 %0, %1, %2;"     : "=l"(sl[j]) : "l"(al), "l"(bl));
        asm("add.rn.f32x2 %0, %1, %2;"     : "=l"(sh[j]) : "l"(ah), "l"(bh));
        asm("fma.rn.f32x2 %0, %1, %2, %3;" : "=l"(dl[j]) : "l"(NEG1), "l"(bl), "l"(al));
        asm("fma.rn.f32x2 %0, %1, %2, %3;" : "=l"(dh[j]) : "l"(NEG1), "l"(bh), "l"(ah));
    }
    __syncthreads();

    // ---- 8 folded rows: u = E[t]·s, v = O[t]·d ----
    #pragma unroll
    for (int t = 0; t < 8; t++) {
        unsigned long long ul = 0ull, uh = 0ull, vl = 0ull, vh = 0ull;
        #pragma unroll
        for (int j2 = 0; j2 < 4; j2++) {
            const ulonglong2 e = *(const ulonglong2*)&sEm[t][2 * j2];  // LDS.128
            const ulonglong2 o = *(const ulonglong2*)&sOm[t][2 * j2];  // LDS.128
            asm("fma.rn.f32x2 %0, %1, %2, %0;" : "+l"(ul) : "l"(e.x), "l"(sl[2*j2  ]));
            asm("fma.rn.f32x2 %0, %1, %2, %0;" : "+l"(uh) : "l"(e.x), "l"(sh[2*j2  ]));
            asm("fma.rn.f32x2 %0, %1, %2, %0;" : "+l"(ul) : "l"(e.y), "l"(sl[2*j2+1]));
            asm("fma.rn.f32x2 %0, %1, %2, %0;" : "+l"(uh) : "l"(e.y), "l"(sh[2*j2+1]));
            asm("fma.rn.f32x2 %0, %1, %2, %0;" : "+l"(vl) : "l"(o.x), "l"(dl[2*j2  ]));
            asm("fma.rn.f32x2 %0, %1, %2, %0;" : "+l"(vh) : "l"(o.x), "l"(dh[2*j2  ]));
            asm("fma.rn.f32x2 %0, %1, %2, %0;" : "+l"(vl) : "l"(o.y), "l"(dl[2*j2+1]));
            asm("fma.rn.f32x2 %0, %1, %2, %0;" : "+l"(vh) : "l"(o.y), "l"(dh[2*j2+1]));
        }
        longlong2 ya, yb;
        unsigned long long w0, w1;
        asm("add.rn.f32x2 %0, %1, %2;" : "=l"(w0) : "l"(ul), "l"(vl));
        asm("add.rn.f32x2 %0, %1, %2;" : "=l"(w1) : "l"(uh), "l"(vh));
        ya.x = (long long)w0; ya.y = (long long)w1;
        asm("fma.rn.f32x2 %0, %1, %2, %3;" : "=l"(w0) : "l"(NEG1), "l"(vl), "l"(ul));
        asm("fma.rn.f32x2 %0, %1, %2, %3;" : "=l"(w1) : "l"(NEG1), "l"(vh), "l"(uh));
        yb.x = (long long)w0; yb.y = (long long)w1;
        __stcs(out + base + (size_t)t * HW4, ya);
        __stcs(out + base + (size_t)(15 - t) * HW4, yb);
    }
}

// ---------------------------------------------------------------------------
extern "C" void kernel_launch(void* const* d_in, const int* in_sizes, int n_in,
                              void* d_out, int out_size)
{
    const float* r  = (const float*)d_in[0];   // (8,64,16,64,64)
    const float* E  = (const float*)d_in[1];   // (8,768)
    const float* Wf = (const float*)d_in[2];   // (1024,768)
    const float* bf = (const float*)d_in[3];   // (1024,)
    float* out = (float*)d_out;

    gate_kernel<<<NC, 256>>>(E, Wf, bf);

    dim3 grid(NBC, 4);
    mod_kernel<<<grid, 256>>>((const longlong2*)r, (longlong2*)out);
}